// round 11
// baseline (speedup 1.0000x reference)
#include <cuda_runtime.h>
#include <cuda_fp16.h>
#include <cstddef>

// Problem dims (fixed): (B=2, C=1, D=160, H=192, W=160) fp32, WIN=9 box, zero pad
#define Bn 2
#define Dn 160
#define Hn 192
#define Wn 160
#define Rr 4
#define HW (Hn*Wn)
#define DHW (Dn*HW)
#define NB (Bn*DHW)          // 9,830,400 outputs
#define NCH 5
#define NQ (Wn/4)            // 40 w-quads

// K1 (H-filter) decomposition
#define HSPLIT 4
#define HCHUNK (Hn/HSPLIT)   // 48
#define HSUB (HCHUNK/4)      // 12 output rows per thread

// K2: quad thread, 4 h-rows/block, DSPLIT=10, unroll 4
#define DSPLIT 10
#define DCHUNK (Dn/DSPLIT)   // 16
#define NROWS 4
#define NPART (Bn*(Hn/NROWS)*DSPLIT)   // 960

#define SROW 42              // padded quad row: [0]=left pad, [41]=right pad

// Scratch TRANSPOSED fp16 with padded D axis:
//   [ch][b][h][dp][w],  dp = d + PADLO,  dp in [0, DP)
// Pads (dp<PADLO or dp>=PADLO+Dn) are zero -> K2 loop is branch-free.
#define DP 176
#define PADLO 8
#define NBP ((size_t)Bn*Hn*DP*Wn)      // 10,813,440 els per channel
__device__ uint2 g_buf[NCH * NBP / 4]; // ~108.1 MB, 8B-aligned
__device__ double g_part[NPART];
__device__ unsigned int g_done = 0;

__device__ __forceinline__ float4 f4zero() { return make_float4(0.f,0.f,0.f,0.f); }
#define ADD4(S,V) do{ S.x+=V.x; S.y+=V.y; S.z+=V.z; S.w+=V.w; }while(0)
#define SUB4(S,V) do{ S.x-=V.x; S.y-=V.y; S.z-=V.z; S.w-=V.w; }while(0)

// one 8B load -> 4 floats
__device__ __forceinline__ float4 ldh4(const __half* a) {
    const uint2 u = *(const uint2*)a;
    const __half2 h0 = *(const __half2*)&u.x;
    const __half2 h1 = *(const __half2*)&u.y;
    const float2 lo = __half22float2(h0);
    const float2 hi = __half22float2(h1);
    return make_float4(lo.x, lo.y, hi.x, hi.y);
}
// 4 floats -> one 8B store
__device__ __forceinline__ void sth4(__half* a, float4 v) {
    const __half2 h0 = __floats2half2_rn(v.x, v.y);
    const __half2 h1 = __floats2half2_rn(v.z, v.w);
    uint2 u;
    u.x = *(const unsigned*)&h0;
    u.y = *(const unsigned*)&h1;
    *(uint2*)a = u;
}

// 12 consecutive values -> four 9-tap sliding sums
__device__ __forceinline__ float4 slide9(const float v[12]) {
    float s = v[0]+v[1]+v[2]+v[3]+v[4]+v[5]+v[6]+v[7]+v[8];
    float4 o;
    o.x = s; s += v[9]  - v[0];
    o.y = s; s += v[10] - v[1];
    o.z = s; s += v[11] - v[2];
    o.w = s;
    return o;
}

// ---------------------------------------------------------------------------
// K0: zero the D pads of the scratch (16 planes per (ch,b,h) row).
// Grid: NCH*Bn*Hn = 1920 blocks, 160 threads; coalesced 320B rows.
// ---------------------------------------------------------------------------
__global__ void __launch_bounds__(160)
zero_pads(__half* __restrict__ buf) {
    const int blk = blockIdx.x;
    const int h   = blk % Hn;
    const int rem = blk / Hn;
    const int b   = rem % Bn;
    const int ch  = rem / Bn;
    const int t   = threadIdx.x;

    __half* base = buf + (size_t)ch * NBP + ((size_t)(b*Hn + h) * DP) * Wn + t;
#pragma unroll
    for (int k = 0; k < 2*PADLO; ++k) {
        const int dp = (k < PADLO) ? k : (PADLO + Dn + k - PADLO);
        base[(size_t)dp * Wn] = __half(0);
    }
}

// ---------------------------------------------------------------------------
// K1: 9-tap H-filter on raw voxels, 5 stat channels, fp32 accumulate.
// Rolling window along h; subtract side reloads the raw row (L1 hit, exact
// telescoping). Writes TRANSPOSED padded fp16 scratch [ch][b][h][dp][w].
// ---------------------------------------------------------------------------
__global__ void __launch_bounds__(160)
pass_h(const float* __restrict__ I, const float* __restrict__ J,
       __half* __restrict__ out) {
    const int blk = blockIdx.x;
    const int hs  = blk % HSPLIT;
    const int rem = blk / HSPLIT;
    const int d   = rem % Dn;
    const int b   = rem / Dn;

    const int tid  = threadIdx.x;
    const int wq   = tid % NQ;
    const int hsub = tid / NQ;                 // 0..3
    const int hbeg = hs * HCHUNK + hsub * HSUB;

    const size_t pbase = (size_t)b * DHW + (size_t)d * HW + 4*wq;
    const float* bI = I + pbase;
    const float* bJ = J + pbase;
    __half* bO = out + ((size_t)(b*Hn) * DP + (d + PADLO)) * Wn + 4*wq;

    float4 S0=f4zero(), S1=f4zero(), S2=f4zero(), S3=f4zero(), S4=f4zero();

    for (int r = hbeg - Rr; r <= hbeg + HSUB + Rr - 1; ++r) {
        if ((unsigned)r < (unsigned)Hn) {
            const float4 a = *(const float4*)(bI + (size_t)r * Wn);
            const float4 q = *(const float4*)(bJ + (size_t)r * Wn);
            ADD4(S0,a); ADD4(S1,q);
            S2.x += a.x*a.x; S2.y += a.y*a.y; S2.z += a.z*a.z; S2.w += a.w*a.w;
            S3.x += q.x*q.x; S3.y += q.y*q.y; S3.z += q.z*q.z; S3.w += q.w*q.w;
            S4.x += a.x*q.x; S4.y += a.y*q.y; S4.z += a.z*q.z; S4.w += a.w*q.w;
        }
        const int o = r - Rr;
        if (o >= hbeg) {
            __half* op = bO + (size_t)o * (DP * Wn);
            sth4(op + 0*NBP, S0);
            sth4(op + 1*NBP, S1);
            sth4(op + 2*NBP, S2);
            sth4(op + 3*NBP, S3);
            sth4(op + 4*NBP, S4);

            const int qr = o - Rr;             // row leaving the window
            if (qr >= 0) {
                const float4 a = *(const float4*)(bI + (size_t)qr * Wn);
                const float4 q = *(const float4*)(bJ + (size_t)qr * Wn);
                SUB4(S0,a); SUB4(S1,q);
                S2.x -= a.x*a.x; S2.y -= a.y*a.y; S2.z -= a.z*a.z; S2.w -= a.w*a.w;
                S3.x -= q.x*q.x; S3.y -= q.y*q.y; S3.z -= q.z*q.z; S3.w -= q.w*q.w;
                S4.x -= a.x*q.x; S4.y -= a.y*q.y; S4.z -= a.z*q.z; S4.w -= a.w*q.w;
            }
        }
    }
}

// ---------------------------------------------------------------------------
// K2: branch-free D-filter (float4 rolling window on padded fp16 H-sums;
// subtract reloads L2-resident), W 9-tap via double-buffered smem rows,
// cc + global mean. 4x unrolled D loop with immediate-offset loads.
// Block: 160 = 40 quads x 4 h-rows. Grid: 960 (6 blocks/SM resident).
// ---------------------------------------------------------------------------
__global__ void __launch_bounds__(160, 6)
pass_d_w_cc(const __half* __restrict__ in, float* __restrict__ outscalar) {
    __shared__ float4 sbuf[2][NROWS][NCH][SROW];

    const int blk   = blockIdx.x;
    const int chunk = blk % DSPLIT;
    const int id    = blk / DSPLIT;
    const int hg    = id % (Hn/NROWS);
    const int b     = id / (Hn/NROWS);

    const int tid  = threadIdx.x;
    const int wq   = tid % NQ;
    const int row4 = tid / NQ;                 // 0..3
    const int h    = hg * NROWS + row4;

    // per-channel base pointers at d=0 for this (b,h,quad)
    const __half* pc0 = in + 0*NBP + ((size_t)(b*Hn + h) * DP + PADLO) * Wn + 4*wq;
    const __half* pc1 = pc0 + 1*NBP;
    const __half* pc2 = pc0 + 2*NBP;
    const __half* pc3 = pc0 + 3*NBP;
    const __half* pc4 = pc0 + 4*NBP;

    const int o0 = chunk * DCHUNK;

    // zero the W pads once (both buffers): 2*4*5*2 = 80 float4s
    for (int i = tid; i < 80; i += 160) {
        const int side = i & 1;
        const int ch   = (i >> 1) % NCH;
        const int rr   = ((i >> 1) / NCH) % NROWS;
        const int bf   = (i >> 1) / (NCH * NROWS);
        sbuf[bf][rr][ch][side ? (SROW-1) : 0] = f4zero();
    }

    // init D window: planes [o0-4 .. o0+4] — pads make this unconditional
    float4 S0=f4zero(), S1=f4zero(), S2=f4zero(), S3=f4zero(), S4=f4zero();
#pragma unroll
    for (int k = -Rr; k <= Rr; ++k) {
        const ptrdiff_t off = (ptrdiff_t)(o0 + k) * Wn;
        float4 v;
        v = ldh4(pc0 + off); ADD4(S0,v);
        v = ldh4(pc1 + off); ADD4(S1,v);
        v = ldh4(pc2 + off); ADD4(S2,v);
        v = ldh4(pc3 + off); ADD4(S3,v);
        v = ldh4(pc4 + off); ADD4(S4,v);
    }

    const float inv = 1.0f / 729.0f;
    float accf = 0.f;

    for (int oo = o0; oo < o0 + DCHUNK; oo += 4) {
        // add-side base pointers for this 4-group (imm offsets u*Wn, (u-9)*Wn)
        const __half* r0 = pc0 + (ptrdiff_t)(oo + Rr + 1) * Wn;
        const __half* r1 = pc1 + (ptrdiff_t)(oo + Rr + 1) * Wn;
        const __half* r2 = pc2 + (ptrdiff_t)(oo + Rr + 1) * Wn;
        const __half* r3 = pc3 + (ptrdiff_t)(oo + Rr + 1) * Wn;
        const __half* r4 = pc4 + (ptrdiff_t)(oo + Rr + 1) * Wn;

#pragma unroll
        for (int u = 0; u < 4; ++u) {
            const int buf = (oo + u) & 1;
            sbuf[buf][row4][0][1+wq] = S0;
            sbuf[buf][row4][1][1+wq] = S1;
            sbuf[buf][row4][2][1+wq] = S2;
            sbuf[buf][row4][3][1+wq] = S3;
            sbuf[buf][row4][4][1+wq] = S4;
            __syncthreads();

            // W 9-tap from smem (pads give zero boundary), then cc
            float4 W[NCH];
#pragma unroll
            for (int ch = 0; ch < NCH; ++ch) {
                const float4 L = sbuf[buf][row4][ch][wq];
                const float4 C = sbuf[buf][row4][ch][1+wq];
                const float4 R = sbuf[buf][row4][ch][2+wq];
                const float v[12] = {L.x,L.y,L.z,L.w, C.x,C.y,C.z,C.w, R.x,R.y,R.z,R.w};
                W[ch] = slide9(v);
            }
            {
                const float mu1=W[0].x*inv, mu2=W[1].x*inv;
                const float v1=W[2].x*inv-mu1*mu1, v2=W[3].x*inv-mu2*mu2, cv=W[4].x*inv-mu1*mu2;
                accf += __fdividef(cv*cv, v1*v2 + 1e-5f);
            }
            {
                const float mu1=W[0].y*inv, mu2=W[1].y*inv;
                const float v1=W[2].y*inv-mu1*mu1, v2=W[3].y*inv-mu2*mu2, cv=W[4].y*inv-mu1*mu2;
                accf += __fdividef(cv*cv, v1*v2 + 1e-5f);
            }
            {
                const float mu1=W[0].z*inv, mu2=W[1].z*inv;
                const float v1=W[2].z*inv-mu1*mu1, v2=W[3].z*inv-mu2*mu2, cv=W[4].z*inv-mu1*mu2;
                accf += __fdividef(cv*cv, v1*v2 + 1e-5f);
            }
            {
                const float mu1=W[0].w*inv, mu2=W[1].w*inv;
                const float v1=W[2].w*inv-mu1*mu1, v2=W[3].w*inv-mu2*mu2, cv=W[4].w*inv-mu1*mu2;
                accf += __fdividef(cv*cv, v1*v2 + 1e-5f);
            }

            // branch-free window advance: add plane o+5, drop plane o-4
            {
                float4 v;
                v = ldh4(r0 + u*Wn); ADD4(S0,v);
                v = ldh4(r1 + u*Wn); ADD4(S1,v);
                v = ldh4(r2 + u*Wn); ADD4(S2,v);
                v = ldh4(r3 + u*Wn); ADD4(S3,v);
                v = ldh4(r4 + u*Wn); ADD4(S4,v);
                v = ldh4(r0 + (u-9)*Wn); SUB4(S0,v);
                v = ldh4(r1 + (u-9)*Wn); SUB4(S1,v);
                v = ldh4(r2 + (u-9)*Wn); SUB4(S2,v);
                v = ldh4(r3 + (u-9)*Wn); SUB4(S3,v);
                v = ldh4(r4 + (u-9)*Wn); SUB4(S4,v);
            }
        }
    }

    // Deterministic block reduction (160 -> 1)
    __shared__ double red[160];
    const int w = tid;
    red[w] = (double)accf;
    __syncthreads();
    if (w < 32) red[w] += red[w + 128];
    __syncthreads();
#pragma unroll
    for (int s = 64; s > 0; s >>= 1) {
        if (w < s) red[w] += red[w + s];
        __syncthreads();
    }

    __shared__ int isLast;
    if (w == 0) {
        g_part[blk] = red[0];
        __threadfence();
        const unsigned v = atomicAdd(&g_done, 1u);
        isLast = (v == (unsigned)(gridDim.x - 1));
    }
    __syncthreads();

    if (isLast) {
        __threadfence();
        double a = 0.0;
        for (int i = w; i < NPART; i += 160) a += g_part[i];  // fixed order
        red[w] = a;
        __syncthreads();
        if (w < 32) red[w] += red[w + 128];
        __syncthreads();
#pragma unroll
        for (int s = 64; s > 0; s >>= 1) {
            if (w < s) red[w] += red[w + s];
            __syncthreads();
        }
        if (w == 0) {
            outscalar[0] = (float)(-red[0] / (double)NB);
            g_done = 0;   // reset for next graph replay
        }
    }
}

extern "C" void kernel_launch(void* const* d_in, const int* in_sizes, int n_in,
                              void* d_out, int out_size) {
    const float* I = (const float*)d_in[0];   // y_true
    const float* J = (const float*)d_in[1];   // y_pred
    float* out = (float*)d_out;

    void* bufraw;
    cudaGetSymbolAddress(&bufraw, g_buf);
    __half* buf = (__half*)bufraw;

    zero_pads<<<NCH * Bn * Hn, 160>>>(buf);
    pass_h<<<Bn * Dn * HSPLIT, 160>>>(I, J, buf);
    pass_d_w_cc<<<Bn * (Hn/NROWS) * DSPLIT, 160>>>(buf, out);
}

// round 12
// speedup vs baseline: 2.0115x; 2.0115x over previous
#include <cuda_runtime.h>
#include <cuda_fp16.h>
#include <cstddef>

// Problem dims (fixed): (B=2, C=1, D=160, H=192, W=160) fp32, WIN=9 box, zero pad
#define Bn 2
#define Dn 160
#define Hn 192
#define Wn 160
#define Rr 4
#define HW (Hn*Wn)
#define DHW (Dn*HW)
#define NB (Bn*DHW)          // 9,830,400 outputs
#define NCH 5
#define NQ (Wn/4)            // 40 w-quads

// K1 (fused W+H filter) decomposition
#define HSPLIT 4
#define HCHUNK (Hn/HSPLIT)   // 48
#define HSUB (HCHUNK/4)      // 12 output rows per thread

// K2 (D-filter + cc): quad thread, 4 h-rows/block, DSPLIT=8
#define DSPLIT 8
#define DCHUNK (Dn/DSPLIT)   // 20
#define NROWS 4
#define NPART (Bn*(Hn/NROWS)*DSPLIT)   // 768

// Scratch TRANSPOSED fp16 with padded D axis, holding WH-filtered sums:
//   [ch][b][h][dp][w],  dp = d + PADLO,  dp in [0, DP)
// Pad planes are NEVER written; __device__ globals are zero-initialized,
// so they are permanently zero -> K2's D loop is branch-free.
#define DP 176
#define PADLO 8
#define NBP ((size_t)Bn*Hn*DP*Wn)      // 10,813,440 els per channel
__device__ uint2 g_buf[NCH * NBP / 4]; // ~108.1 MB, 8B-aligned, zero-init
__device__ double g_part[NPART];
__device__ unsigned int g_done = 0;

__device__ __forceinline__ float4 f4zero() { return make_float4(0.f,0.f,0.f,0.f); }
#define ADD4(S,V) do{ S.x+=V.x; S.y+=V.y; S.z+=V.z; S.w+=V.w; }while(0)
#define SUB4(S,V) do{ S.x-=V.x; S.y-=V.y; S.z-=V.z; S.w-=V.w; }while(0)

// one 8B load -> 4 floats
__device__ __forceinline__ float4 ldh4(const __half* a) {
    const uint2 u = *(const uint2*)a;
    const __half2 h0 = *(const __half2*)&u.x;
    const __half2 h1 = *(const __half2*)&u.y;
    const float2 lo = __half22float2(h0);
    const float2 hi = __half22float2(h1);
    return make_float4(lo.x, lo.y, hi.x, hi.y);
}
// 4 floats -> one 8B store
__device__ __forceinline__ void sth4(__half* a, float4 v) {
    const __half2 h0 = __floats2half2_rn(v.x, v.y);
    const __half2 h1 = __floats2half2_rn(v.z, v.w);
    uint2 u;
    u.x = *(const unsigned*)&h0;
    u.y = *(const unsigned*)&h1;
    *(uint2*)a = u;
}

// 12 consecutive values -> four 9-tap sliding sums
__device__ __forceinline__ float4 slide9(const float v[12]) {
    float s = v[0]+v[1]+v[2]+v[3]+v[4]+v[5]+v[6]+v[7]+v[8];
    float4 o;
    o.x = s; s += v[9]  - v[0];
    o.y = s; s += v[10] - v[1];
    o.z = s; s += v[11] - v[2];
    o.w = s;
    return o;
}

// One raw row's 12-value neighborhood for a w-quad (zero-padded at W edges)
// -> the 5 channel 9-tap W-sums.
__device__ __forceinline__ void row_wsums(const float* __restrict__ rI,
                                          const float* __restrict__ rJ,
                                          int wq,
                                          float4& w0, float4& w1, float4& w2,
                                          float4& w3, float4& w4) {
    const float4 aL = (wq > 0)      ? *(const float4*)(rI - 4) : f4zero();
    const float4 aC =                 *(const float4*)(rI);
    const float4 aR = (wq < NQ - 1) ? *(const float4*)(rI + 4) : f4zero();
    const float4 bL = (wq > 0)      ? *(const float4*)(rJ - 4) : f4zero();
    const float4 bC =                 *(const float4*)(rJ);
    const float4 bR = (wq < NQ - 1) ? *(const float4*)(rJ + 4) : f4zero();

    float x[12] = {aL.x,aL.y,aL.z,aL.w, aC.x,aC.y,aC.z,aC.w, aR.x,aR.y,aR.z,aR.w};
    float y[12] = {bL.x,bL.y,bL.z,bL.w, bC.x,bC.y,bC.z,bC.w, bR.x,bR.y,bR.z,bR.w};

    w0 = slide9(x);
    w1 = slide9(y);
    float t[12];
#pragma unroll
    for (int k = 0; k < 12; ++k) t[k] = x[k]*x[k];
    w2 = slide9(t);
#pragma unroll
    for (int k = 0; k < 12; ++k) t[k] = y[k]*y[k];
    w3 = slide9(t);
#pragma unroll
    for (int k = 0; k < 12; ++k) t[k] = x[k]*y[k];
    w4 = slide9(t);
}

// ---------------------------------------------------------------------------
// K1: fused W+H 9-tap box sums (5 stat channels), fp32 accumulate, no smem,
// no syncs. Rolling H window; subtract side recomputes the leaving row's
// W-sums from L1-resident raw rows (exact telescoping). Stores fp16
// WH-sums into the TRANSPOSED padded scratch [ch][b][h][dp][w].
// Thread = one w-quad, one 12-row h substream. Grid: Bn*Dn*HSPLIT = 1280.
// ---------------------------------------------------------------------------
__global__ void __launch_bounds__(160)
pass_wh(const float* __restrict__ I, const float* __restrict__ J,
        __half* __restrict__ out) {
    const int blk = blockIdx.x;
    const int hs  = blk % HSPLIT;
    const int rem = blk / HSPLIT;
    const int d   = rem % Dn;
    const int b   = rem / Dn;

    const int tid  = threadIdx.x;
    const int wq   = tid % NQ;
    const int hsub = tid / NQ;                 // 0..3
    const int hbeg = hs * HCHUNK + hsub * HSUB;

    const size_t pbase = (size_t)b * DHW + (size_t)d * HW + 4*wq;
    const float* bI = I + pbase;
    const float* bJ = J + pbase;
    // transposed store base: h gets added per output row
    __half* bO = out + ((size_t)(b*Hn) * DP + (d + PADLO)) * Wn + 4*wq;

    float4 S0=f4zero(), S1=f4zero(), S2=f4zero(), S3=f4zero(), S4=f4zero();

    for (int r = hbeg - Rr; r <= hbeg + HSUB + Rr - 1; ++r) {
        if ((unsigned)r < (unsigned)Hn) {
            float4 w0,w1,w2,w3,w4;
            row_wsums(bI + (size_t)r*Wn, bJ + (size_t)r*Wn, wq,
                      w0,w1,w2,w3,w4);
            ADD4(S0,w0); ADD4(S1,w1); ADD4(S2,w2); ADD4(S3,w3); ADD4(S4,w4);
        }
        const int o = r - Rr;
        if (o >= hbeg) {
            __half* op = bO + (size_t)o * (DP * Wn);
            sth4(op + 0*NBP, S0);
            sth4(op + 1*NBP, S1);
            sth4(op + 2*NBP, S2);
            sth4(op + 3*NBP, S3);
            sth4(op + 4*NBP, S4);

            const int qr = r - 2*Rr;           // row leaving the window
            if (qr >= 0) {
                float4 w0,w1,w2,w3,w4;
                row_wsums(bI + (size_t)qr*Wn, bJ + (size_t)qr*Wn, wq,
                          w0,w1,w2,w3,w4);
                SUB4(S0,w0); SUB4(S1,w1); SUB4(S2,w2); SUB4(S3,w3); SUB4(S4,w4);
            }
        }
    }
}

// ---------------------------------------------------------------------------
// K2: trivial branch-free D-filter on fp16 WH-sums + cc + global mean.
// Register rolling window; add streams 320B-stride, subtract reloads are
// L1/L2-resident; pads make everything unconditional. No smem stage, no
// per-plane syncs. Block: 160 = 40 quads x 4 h-rows. Grid: 768.
// ---------------------------------------------------------------------------
__global__ void __launch_bounds__(160)
pass_d_cc(const __half* __restrict__ in, float* __restrict__ outscalar) {
    const int blk   = blockIdx.x;
    const int chunk = blk % DSPLIT;
    const int id    = blk / DSPLIT;
    const int hg    = id % (Hn/NROWS);
    const int b     = id / (Hn/NROWS);

    const int tid  = threadIdx.x;
    const int wq   = tid % NQ;
    const int row4 = tid / NQ;                 // 0..3
    const int h    = hg * NROWS + row4;

    // per-channel base pointers at d=0 for this (b,h,quad)
    const __half* pc0 = in + ((size_t)(b*Hn + h) * DP + PADLO) * Wn + 4*wq;
    const __half* pc1 = pc0 + 1*NBP;
    const __half* pc2 = pc0 + 2*NBP;
    const __half* pc3 = pc0 + 3*NBP;
    const __half* pc4 = pc0 + 4*NBP;

    const int o0 = chunk * DCHUNK;

    // init D window: planes [o0-4 .. o0+4] — pads make this unconditional
    float4 S0=f4zero(), S1=f4zero(), S2=f4zero(), S3=f4zero(), S4=f4zero();
#pragma unroll
    for (int k = -Rr; k <= Rr; ++k) {
        const ptrdiff_t off = (ptrdiff_t)(o0 + k) * Wn;
        float4 v;
        v = ldh4(pc0 + off); ADD4(S0,v);
        v = ldh4(pc1 + off); ADD4(S1,v);
        v = ldh4(pc2 + off); ADD4(S2,v);
        v = ldh4(pc3 + off); ADD4(S3,v);
        v = ldh4(pc4 + off); ADD4(S4,v);
    }

    const float inv = 1.0f / 729.0f;
    float accf = 0.f;

    for (int o = o0; o < o0 + DCHUNK; ++o) {
        // cc epilogue on current window [o-4, o+4]
        {
            const float mu1=S0.x*inv, mu2=S1.x*inv;
            const float v1=S2.x*inv-mu1*mu1, v2=S3.x*inv-mu2*mu2, cv=S4.x*inv-mu1*mu2;
            accf += __fdividef(cv*cv, v1*v2 + 1e-5f);
        }
        {
            const float mu1=S0.y*inv, mu2=S1.y*inv;
            const float v1=S2.y*inv-mu1*mu1, v2=S3.y*inv-mu2*mu2, cv=S4.y*inv-mu1*mu2;
            accf += __fdividef(cv*cv, v1*v2 + 1e-5f);
        }
        {
            const float mu1=S0.z*inv, mu2=S1.z*inv;
            const float v1=S2.z*inv-mu1*mu1, v2=S3.z*inv-mu2*mu2, cv=S4.z*inv-mu1*mu2;
            accf += __fdividef(cv*cv, v1*v2 + 1e-5f);
        }
        {
            const float mu1=S0.w*inv, mu2=S1.w*inv;
            const float v1=S2.w*inv-mu1*mu1, v2=S3.w*inv-mu2*mu2, cv=S4.w*inv-mu1*mu2;
            accf += __fdividef(cv*cv, v1*v2 + 1e-5f);
        }

        // branch-free advance: add plane o+5, drop plane o-4 (pads = zero)
        {
            const ptrdiff_t oa = (ptrdiff_t)(o + Rr + 1) * Wn;
            const ptrdiff_t os = (ptrdiff_t)(o - Rr) * Wn;
            float4 v;
            v = ldh4(pc0 + oa); ADD4(S0,v);
            v = ldh4(pc1 + oa); ADD4(S1,v);
            v = ldh4(pc2 + oa); ADD4(S2,v);
            v = ldh4(pc3 + oa); ADD4(S3,v);
            v = ldh4(pc4 + oa); ADD4(S4,v);
            v = ldh4(pc0 + os); SUB4(S0,v);
            v = ldh4(pc1 + os); SUB4(S1,v);
            v = ldh4(pc2 + os); SUB4(S2,v);
            v = ldh4(pc3 + os); SUB4(S3,v);
            v = ldh4(pc4 + os); SUB4(S4,v);
        }
    }

    // Deterministic block reduction (160 -> 1)
    __shared__ double red[160];
    const int w = tid;
    red[w] = (double)accf;
    __syncthreads();
    if (w < 32) red[w] += red[w + 128];
    __syncthreads();
#pragma unroll
    for (int s = 64; s > 0; s >>= 1) {
        if (w < s) red[w] += red[w + s];
        __syncthreads();
    }

    __shared__ int isLast;
    if (w == 0) {
        g_part[blk] = red[0];
        __threadfence();
        const unsigned v = atomicAdd(&g_done, 1u);
        isLast = (v == (unsigned)(gridDim.x - 1));
    }
    __syncthreads();

    if (isLast) {
        __threadfence();
        double a = 0.0;
        for (int i = w; i < NPART; i += 160) a += g_part[i];  // fixed order
        red[w] = a;
        __syncthreads();
        if (w < 32) red[w] += red[w + 128];
        __syncthreads();
#pragma unroll
        for (int s = 64; s > 0; s >>= 1) {
            if (w < s) red[w] += red[w + s];
            __syncthreads();
        }
        if (w == 0) {
            outscalar[0] = (float)(-red[0] / (double)NB);
            g_done = 0;   // reset for next graph replay
        }
    }
}

extern "C" void kernel_launch(void* const* d_in, const int* in_sizes, int n_in,
                              void* d_out, int out_size) {
    const float* I = (const float*)d_in[0];   // y_true
    const float* J = (const float*)d_in[1];   // y_pred
    float* out = (float*)d_out;

    void* bufraw;
    cudaGetSymbolAddress(&bufraw, g_buf);
    __half* buf = (__half*)bufraw;

    pass_wh<<<Bn * Dn * HSPLIT, 160>>>(I, J, buf);
    pass_d_cc<<<Bn * (Hn/NROWS) * DSPLIT, 160>>>(buf, out);
}

// round 13
// speedup vs baseline: 2.0596x; 1.0239x over previous
#include <cuda_runtime.h>
#include <cuda_fp16.h>
#include <cstddef>

// Problem dims (fixed): (B=2, C=1, D=160, H=192, W=160) fp32, WIN=9 box, zero pad
#define Bn 2
#define Dn 160
#define Hn 192
#define Wn 160
#define Rr 4
#define HW (Hn*Wn)
#define DHW (Dn*HW)
#define NB (Bn*DHW)          // 9,830,400 outputs
#define NCH 5
#define NQ (Wn/4)            // 40 w-quads

// K1 (fused W+H filter): HSPLIT=2 cuts halo wsum recomputes (2.67->2.33/out)
#define HSPLIT 2
#define HCHUNK (Hn/HSPLIT)   // 96
#define HSUB (HCHUNK/4)      // 24 output rows per thread

// K2 (D-filter + cc): DSPLIT=10 -> 960 blocks -> ~50% occ, reuse stays in L2
#define DSPLIT 10
#define DCHUNK (Dn/DSPLIT)   // 16
#define NROWS 4
#define NPART (Bn*(Hn/NROWS)*DSPLIT)   // 960

// Scratch TRANSPOSED fp16 with padded D axis, holding WH-filtered sums:
//   [ch][b][h][dp][w],  dp = d + PADLO,  dp in [0, DP)
// Pad planes are NEVER written; __device__ globals are zero-initialized,
// so they are permanently zero -> K2's D loop is branch-free.
#define DP 176
#define PADLO 8
#define NBP ((size_t)Bn*Hn*DP*Wn)      // 10,813,440 els per channel
__device__ uint2 g_buf[NCH * NBP / 4]; // ~108.1 MB, 8B-aligned, zero-init
__device__ double g_part[NPART];
__device__ unsigned int g_done = 0;

__device__ __forceinline__ float4 f4zero() { return make_float4(0.f,0.f,0.f,0.f); }
#define ADD4(S,V) do{ S.x+=V.x; S.y+=V.y; S.z+=V.z; S.w+=V.w; }while(0)
#define SUB4(S,V) do{ S.x-=V.x; S.y-=V.y; S.z-=V.z; S.w-=V.w; }while(0)

// one 8B load -> 4 floats
__device__ __forceinline__ float4 ldh4(const __half* a) {
    const uint2 u = *(const uint2*)a;
    const __half2 h0 = *(const __half2*)&u.x;
    const __half2 h1 = *(const __half2*)&u.y;
    const float2 lo = __half22float2(h0);
    const float2 hi = __half22float2(h1);
    return make_float4(lo.x, lo.y, hi.x, hi.y);
}
// 4 floats -> one 8B store
__device__ __forceinline__ void sth4(__half* a, float4 v) {
    const __half2 h0 = __floats2half2_rn(v.x, v.y);
    const __half2 h1 = __floats2half2_rn(v.z, v.w);
    uint2 u;
    u.x = *(const unsigned*)&h0;
    u.y = *(const unsigned*)&h1;
    *(uint2*)a = u;
}

// 12 consecutive values -> four 9-tap sliding sums
__device__ __forceinline__ float4 slide9(const float v[12]) {
    float s = v[0]+v[1]+v[2]+v[3]+v[4]+v[5]+v[6]+v[7]+v[8];
    float4 o;
    o.x = s; s += v[9]  - v[0];
    o.y = s; s += v[10] - v[1];
    o.z = s; s += v[11] - v[2];
    o.w = s;
    return o;
}

// One raw row's 12-value neighborhood for a w-quad (zero-padded at W edges)
// -> the 5 channel 9-tap W-sums.
__device__ __forceinline__ void row_wsums(const float* __restrict__ rI,
                                          const float* __restrict__ rJ,
                                          int wq,
                                          float4& w0, float4& w1, float4& w2,
                                          float4& w3, float4& w4) {
    const float4 aL = (wq > 0)      ? *(const float4*)(rI - 4) : f4zero();
    const float4 aC =                 *(const float4*)(rI);
    const float4 aR = (wq < NQ - 1) ? *(const float4*)(rI + 4) : f4zero();
    const float4 bL = (wq > 0)      ? *(const float4*)(rJ - 4) : f4zero();
    const float4 bC =                 *(const float4*)(rJ);
    const float4 bR = (wq < NQ - 1) ? *(const float4*)(rJ + 4) : f4zero();

    float x[12] = {aL.x,aL.y,aL.z,aL.w, aC.x,aC.y,aC.z,aC.w, aR.x,aR.y,aR.z,aR.w};
    float y[12] = {bL.x,bL.y,bL.z,bL.w, bC.x,bC.y,bC.z,bC.w, bR.x,bR.y,bR.z,bR.w};

    w0 = slide9(x);
    w1 = slide9(y);
    float t[12];
#pragma unroll
    for (int k = 0; k < 12; ++k) t[k] = x[k]*x[k];
    w2 = slide9(t);
#pragma unroll
    for (int k = 0; k < 12; ++k) t[k] = y[k]*y[k];
    w3 = slide9(t);
#pragma unroll
    for (int k = 0; k < 12; ++k) t[k] = x[k]*y[k];
    w4 = slide9(t);
}

// ---------------------------------------------------------------------------
// K1: fused W+H 9-tap box sums (5 stat channels), fp32 accumulate, no smem,
// no syncs. Rolling H window; subtract side recomputes the leaving row's
// W-sums from L1-resident raw rows (exact telescoping). Stores fp16
// WH-sums into the TRANSPOSED padded scratch [ch][b][h][dp][w].
// Thread = one w-quad, one 24-row h substream. Grid: Bn*Dn*HSPLIT = 640.
// ---------------------------------------------------------------------------
__global__ void __launch_bounds__(160)
pass_wh(const float* __restrict__ I, const float* __restrict__ J,
        __half* __restrict__ out) {
    const int blk = blockIdx.x;
    const int hs  = blk % HSPLIT;
    const int rem = blk / HSPLIT;
    const int d   = rem % Dn;
    const int b   = rem / Dn;

    const int tid  = threadIdx.x;
    const int wq   = tid % NQ;
    const int hsub = tid / NQ;                 // 0..3
    const int hbeg = hs * HCHUNK + hsub * HSUB;

    const size_t pbase = (size_t)b * DHW + (size_t)d * HW + 4*wq;
    const float* bI = I + pbase;
    const float* bJ = J + pbase;
    // transposed store base: h gets added per output row
    __half* bO = out + ((size_t)(b*Hn) * DP + (d + PADLO)) * Wn + 4*wq;

    float4 S0=f4zero(), S1=f4zero(), S2=f4zero(), S3=f4zero(), S4=f4zero();

    for (int r = hbeg - Rr; r <= hbeg + HSUB + Rr - 1; ++r) {
        if ((unsigned)r < (unsigned)Hn) {
            float4 w0,w1,w2,w3,w4;
            row_wsums(bI + (size_t)r*Wn, bJ + (size_t)r*Wn, wq,
                      w0,w1,w2,w3,w4);
            ADD4(S0,w0); ADD4(S1,w1); ADD4(S2,w2); ADD4(S3,w3); ADD4(S4,w4);
        }
        const int o = r - Rr;
        if (o >= hbeg) {
            __half* op = bO + (size_t)o * (DP * Wn);
            sth4(op + 0*NBP, S0);
            sth4(op + 1*NBP, S1);
            sth4(op + 2*NBP, S2);
            sth4(op + 3*NBP, S3);
            sth4(op + 4*NBP, S4);

            const int qr = r - 2*Rr;           // row leaving the window
            if (qr >= 0) {
                float4 w0,w1,w2,w3,w4;
                row_wsums(bI + (size_t)qr*Wn, bJ + (size_t)qr*Wn, wq,
                          w0,w1,w2,w3,w4);
                SUB4(S0,w0); SUB4(S1,w1); SUB4(S2,w2); SUB4(S3,w3); SUB4(S4,w4);
            }
        }
    }
}

// ---------------------------------------------------------------------------
// K2: trivial branch-free D-filter on fp16 WH-sums + cc + global mean.
// Register rolling window; add streams 320B-stride, subtract reloads are
// L1/L2-resident; pads make everything unconditional. No smem stage, no
// per-plane syncs. Block: 160 = 40 quads x 4 h-rows. Grid: 960.
// ---------------------------------------------------------------------------
__global__ void __launch_bounds__(160)
pass_d_cc(const __half* __restrict__ in, float* __restrict__ outscalar) {
    const int blk   = blockIdx.x;
    const int chunk = blk % DSPLIT;
    const int id    = blk / DSPLIT;
    const int hg    = id % (Hn/NROWS);
    const int b     = id / (Hn/NROWS);

    const int tid  = threadIdx.x;
    const int wq   = tid % NQ;
    const int row4 = tid / NQ;                 // 0..3
    const int h    = hg * NROWS + row4;

    // per-channel base pointers at d=0 for this (b,h,quad)
    const __half* pc0 = in + ((size_t)(b*Hn + h) * DP + PADLO) * Wn + 4*wq;
    const __half* pc1 = pc0 + 1*NBP;
    const __half* pc2 = pc0 + 2*NBP;
    const __half* pc3 = pc0 + 3*NBP;
    const __half* pc4 = pc0 + 4*NBP;

    const int o0 = chunk * DCHUNK;

    // init D window: planes [o0-4 .. o0+4] — pads make this unconditional
    float4 S0=f4zero(), S1=f4zero(), S2=f4zero(), S3=f4zero(), S4=f4zero();
#pragma unroll
    for (int k = -Rr; k <= Rr; ++k) {
        const ptrdiff_t off = (ptrdiff_t)(o0 + k) * Wn;
        float4 v;
        v = ldh4(pc0 + off); ADD4(S0,v);
        v = ldh4(pc1 + off); ADD4(S1,v);
        v = ldh4(pc2 + off); ADD4(S2,v);
        v = ldh4(pc3 + off); ADD4(S3,v);
        v = ldh4(pc4 + off); ADD4(S4,v);
    }

    const float inv = 1.0f / 729.0f;
    float accf = 0.f;

    for (int o = o0; o < o0 + DCHUNK; ++o) {
        // cc epilogue on current window [o-4, o+4]
        {
            const float mu1=S0.x*inv, mu2=S1.x*inv;
            const float v1=S2.x*inv-mu1*mu1, v2=S3.x*inv-mu2*mu2, cv=S4.x*inv-mu1*mu2;
            accf += __fdividef(cv*cv, v1*v2 + 1e-5f);
        }
        {
            const float mu1=S0.y*inv, mu2=S1.y*inv;
            const float v1=S2.y*inv-mu1*mu1, v2=S3.y*inv-mu2*mu2, cv=S4.y*inv-mu1*mu2;
            accf += __fdividef(cv*cv, v1*v2 + 1e-5f);
        }
        {
            const float mu1=S0.z*inv, mu2=S1.z*inv;
            const float v1=S2.z*inv-mu1*mu1, v2=S3.z*inv-mu2*mu2, cv=S4.z*inv-mu1*mu2;
            accf += __fdividef(cv*cv, v1*v2 + 1e-5f);
        }
        {
            const float mu1=S0.w*inv, mu2=S1.w*inv;
            const float v1=S2.w*inv-mu1*mu1, v2=S3.w*inv-mu2*mu2, cv=S4.w*inv-mu1*mu2;
            accf += __fdividef(cv*cv, v1*v2 + 1e-5f);
        }

        // branch-free advance: add plane o+5, drop plane o-4 (pads = zero)
        {
            const ptrdiff_t oa = (ptrdiff_t)(o + Rr + 1) * Wn;
            const ptrdiff_t os = (ptrdiff_t)(o - Rr) * Wn;
            float4 v;
            v = ldh4(pc0 + oa); ADD4(S0,v);
            v = ldh4(pc1 + oa); ADD4(S1,v);
            v = ldh4(pc2 + oa); ADD4(S2,v);
            v = ldh4(pc3 + oa); ADD4(S3,v);
            v = ldh4(pc4 + oa); ADD4(S4,v);
            v = ldh4(pc0 + os); SUB4(S0,v);
            v = ldh4(pc1 + os); SUB4(S1,v);
            v = ldh4(pc2 + os); SUB4(S2,v);
            v = ldh4(pc3 + os); SUB4(S3,v);
            v = ldh4(pc4 + os); SUB4(S4,v);
        }
    }

    // Deterministic block reduction (160 -> 1)
    __shared__ double red[160];
    const int w = tid;
    red[w] = (double)accf;
    __syncthreads();
    if (w < 32) red[w] += red[w + 128];
    __syncthreads();
#pragma unroll
    for (int s = 64; s > 0; s >>= 1) {
        if (w < s) red[w] += red[w + s];
        __syncthreads();
    }

    __shared__ int isLast;
    if (w == 0) {
        g_part[blk] = red[0];
        __threadfence();
        const unsigned v = atomicAdd(&g_done, 1u);
        isLast = (v == (unsigned)(gridDim.x - 1));
    }
    __syncthreads();

    if (isLast) {
        __threadfence();
        double a = 0.0;
        for (int i = w; i < NPART; i += 160) a += g_part[i];  // fixed order
        red[w] = a;
        __syncthreads();
        if (w < 32) red[w] += red[w + 128];
        __syncthreads();
#pragma unroll
        for (int s = 64; s > 0; s >>= 1) {
            if (w < s) red[w] += red[w + s];
            __syncthreads();
        }
        if (w == 0) {
            outscalar[0] = (float)(-red[0] / (double)NB);
            g_done = 0;   // reset for next graph replay
        }
    }
}

extern "C" void kernel_launch(void* const* d_in, const int* in_sizes, int n_in,
                              void* d_out, int out_size) {
    const float* I = (const float*)d_in[0];   // y_true
    const float* J = (const float*)d_in[1];   // y_pred
    float* out = (float*)d_out;

    void* bufraw;
    cudaGetSymbolAddress(&bufraw, g_buf);
    __half* buf = (__half*)bufraw;

    pass_wh<<<Bn * Dn * HSPLIT, 160>>>(I, J, buf);
    pass_d_cc<<<Bn * (Hn/NROWS) * DSPLIT, 160>>>(buf, out);
}